// round 6
// baseline (speedup 1.0000x reference)
#include <cuda_runtime.h>
#include <cuda_bf16.h>
#include <cub/cub.cuh>

#define BB    90
#define LOGN  18
#define NN    (1 << LOGN)            // 262144
#define TOT   (BB * NN)              // 23,592,960
#define DIGB  18
#define NBC   1024                   // coarse buckets per row
#define NCH   (2 * BB * NBC)         // 184,320 coarse counters
#define CAP   4096                   // smem capacity per coarse bucket

// -------- static device scratch --------
static __device__ __align__(256) unsigned long long g_fk[2 * TOT];   // 378 MB records
static __device__ __align__(256) unsigned int g_u2[TOT];             // 94 MB: 2*rank(pred) by idx
static __device__ __align__(256) unsigned int g_ch[NCH];             // coarse counts
static __device__ __align__(256) unsigned int g_cs[NCH];             // coarse starts (scan)
static __device__ __align__(256) unsigned int g_cur[NCH];            // scatter cursors / ends
static __device__ __align__(256) unsigned char g_temp[4u << 20];
static __device__ unsigned long long g_sxx[BB], g_syy[BB], g_sxy[BB];

__device__ __forceinline__ unsigned int fkey(float f) {
    f = f + 0.0f;
    unsigned int u = __float_as_uint(f);
    return (u & 0x80000000u) ? ~u : (u | 0x80000000u);
}
// exactly weakly-monotone 18-bit bucketization (ties never split)
__device__ __forceinline__ unsigned int digit_of(float x) {
    float t = fmaf(x, 32768.0f, 131072.0f);
    t = fminf(fmaxf(t, 0.0f), 262143.0f);
    return (unsigned int)t;
}

__global__ void zero_sums_kernel() {
    int t = threadIdx.x;
    if (t < BB) { g_sxx[t] = 0ull; g_syy[t] = 0ull; g_sxy[t] = 0ull; }
}

// -------- pass 1: coarse histogram (L2-resident counters) --------
__global__ void hist_kernel(const float4* __restrict__ p, const float4* __restrict__ t) {
    int q = blockIdx.x * 256 + threadIdx.x;
    float4 a = p[q], b = t[q];
    unsigned int row = (unsigned int)q >> (LOGN - 2);
    unsigned int ba = row * NBC;
    unsigned int bb = (unsigned int)(BB * NBC) + row * NBC;
    atomicAdd(&g_ch[ba + (digit_of(a.x) >> 8)], 1u);
    atomicAdd(&g_ch[ba + (digit_of(a.y) >> 8)], 1u);
    atomicAdd(&g_ch[ba + (digit_of(a.z) >> 8)], 1u);
    atomicAdd(&g_ch[ba + (digit_of(a.w) >> 8)], 1u);
    atomicAdd(&g_ch[bb + (digit_of(b.x) >> 8)], 1u);
    atomicAdd(&g_ch[bb + (digit_of(b.y) >> 8)], 1u);
    atomicAdd(&g_ch[bb + (digit_of(b.z) >> 8)], 1u);
    atomicAdd(&g_ch[bb + (digit_of(b.w) >> 8)], 1u);
}

// -------- pass 2: scatter records [fkey:32|fine:8@18|idx:18] --------
__global__ void scatter_kernel(const float4* __restrict__ p, const float4* __restrict__ t) {
    int q = blockIdx.x * 256 + threadIdx.x;
    float4 a = p[q], b = t[q];
    unsigned int row  = (unsigned int)q >> (LOGN - 2);
    unsigned int idx0 = ((unsigned int)q << 2) & (NN - 1);
    unsigned int ba = row * NBC;
    unsigned int bb = (unsigned int)(BB * NBC) + row * NBC;
    float av[4] = {a.x, a.y, a.z, a.w};
    float bv[4] = {b.x, b.y, b.z, b.w};
#pragma unroll
    for (int j = 0; j < 4; ++j) {
        unsigned int d = digit_of(av[j]);
        unsigned int pos = atomicAdd(&g_cur[ba + (d >> 8)], 1u);
        g_fk[pos] = ((unsigned long long)fkey(av[j]) << 32)
                  | ((unsigned long long)(d & 255u) << 18) | (idx0 + j);
    }
#pragma unroll
    for (int j = 0; j < 4; ++j) {
        unsigned int d = digit_of(bv[j]);
        unsigned int pos = atomicAdd(&g_cur[bb + (d >> 8)], 1u);
        g_fk[pos] = ((unsigned long long)fkey(bv[j]) << 32)
                  | ((unsigned long long)(d & 255u) << 18) | (idx0 + j);
    }
}

__device__ __forceinline__ long long block_reduce_ll(long long v, long long* red) {
    for (int o = 16; o; o >>= 1) v += __shfl_down_sync(0xFFFFFFFFu, v, o);
    int w = threadIdx.x >> 5, lane = threadIdx.x & 31;
    if (lane == 0) red[w] = v;
    __syncthreads();
    if (w == 0) {
        v = (lane < 8) ? red[lane] : 0ll;
        for (int o = 4; o; o >>= 1) v += __shfl_down_sync(0xFFFFFFFFu, v, o);
    }
    return v;   // valid in thread 0
}

// -------- per-coarse-bucket rank block (templated on pred/true role) --------
template <int IS_TRUE>
__global__ void rank_kernel() {
    __shared__ unsigned long long s_k[CAP];
    __shared__ unsigned int s_fk[CAP];
    __shared__ unsigned int h[256], hs[256], hcur[256];
    __shared__ long long red[8];

    const unsigned int b   = blockIdx.x + (IS_TRUE ? (unsigned)(BB * NBC) : 0u);
    const unsigned int row = blockIdx.x >> 10;
    const unsigned int start = g_cs[b];
    const unsigned int end   = g_cur[b];
    const int n = (int)(end - start);
    const int tid = threadIdx.x;
    // local base: position of bucket start within this row's array half
    const unsigned int lbase = start - (IS_TRUE ? (unsigned)TOT : 0u) - (row << LOGN);

    long long sA = 0, sB = 0;   // pred: sA=sxx ; true: sA=syy, sB=sxy

    if (n > 0 && n <= CAP) {
        for (int i = tid; i < n; i += 256) s_k[i] = g_fk[start + i];
        h[tid] = 0;
        __syncthreads();
        for (int i = tid; i < n; i += 256)
            atomicAdd(&h[(unsigned)(s_k[i] >> 18) & 255u], 1u);
        __syncthreads();
        // inclusive Hillis-Steele scan of h into hs
        unsigned int v = h[tid];
        hs[tid] = v;
        __syncthreads();
        for (int off = 1; off < 256; off <<= 1) {
            unsigned int t = (tid >= off) ? hs[tid - off] : 0u;
            __syncthreads();
            hs[tid] += t;
            __syncthreads();
        }
        unsigned int ex = hs[tid] - h[tid];
        __syncthreads();
        hs[tid] = ex;           // exclusive starts
        hcur[tid] = ex;         // scatter cursor
        __syncthreads();
        // fine scatter of fkeys in smem
        for (int i = tid; i < n; i += 256) {
            unsigned int fine = (unsigned)(s_k[i] >> 18) & 255u;
            unsigned int pos = atomicAdd(&hcur[fine], 1u);
            s_fk[pos] = (unsigned int)(s_k[i] >> 32);
        }
        __syncthreads();
        // rank each element
        for (int i = tid; i < n; i += 256) {
            unsigned long long rec = s_k[i];
            unsigned int fk   = (unsigned int)(rec >> 32);
            unsigned int fine = (unsigned)(rec >> 18) & 255u;
            unsigned int fs = hs[fine], cnt = h[fine];
            int c_less = 0, c_eq = 1;
            if (cnt > 1u) {
                c_eq = 0;
                for (unsigned int j = fs; j < fs + cnt; ++j) {
                    unsigned int f = s_fk[j];
                    c_less += (f < fk);
                    c_eq   += (f == fk);
                }
            }
            int r2 = 2 * (int)(lbase + fs + (unsigned)c_less) + c_eq + 1;
            unsigned int gi = (row << LOGN) + (unsigned int)(rec & 0x3FFFFu);
            if (IS_TRUE) {
                long long u = (long long)g_u2[gi];
                sA += (long long)r2 * r2;     // syy
                sB += u * (long long)r2;      // sxy
            } else {
                g_u2[gi] = (unsigned int)r2;
                sA += (long long)r2 * r2;     // sxx
            }
        }
    } else if (n > CAP) {
        // safety slow path: rank within whole coarse bucket from gmem
        for (int i = tid; i < n; i += 256) {
            unsigned long long rec = g_fk[start + i];
            unsigned int fk = (unsigned int)(rec >> 32);
            int c_less = 0, c_eq = 0;
            for (int j = 0; j < n; ++j) {
                unsigned int f = (unsigned int)(__ldg(&g_fk[start + j]) >> 32);
                c_less += (f < fk);
                c_eq   += (f == fk);
            }
            int r2 = 2 * (int)(lbase + (unsigned)c_less) + c_eq + 1;
            unsigned int gi = (row << LOGN) + (unsigned int)(rec & 0x3FFFFu);
            if (IS_TRUE) {
                long long u = (long long)g_u2[gi];
                sA += (long long)r2 * r2;
                sB += u * (long long)r2;
            } else {
                g_u2[gi] = (unsigned int)r2;
                sA += (long long)r2 * r2;
            }
        }
    } else {
        return;   // n == 0, uniform across block
    }

    __syncthreads();
    sA = block_reduce_ll(sA, red);
    __syncthreads();
    if (IS_TRUE) { sB = block_reduce_ll(sB, red); }
    if (tid == 0) {
        if (IS_TRUE) {
            atomicAdd(&g_syy[row], (unsigned long long)sA);
            atomicAdd(&g_sxy[row], (unsigned long long)sB);
        } else {
            atomicAdd(&g_sxx[row], (unsigned long long)sA);
        }
    }
}

// -------- final: per-row corr -> ICIR loss --------
__global__ void final_kernel(float* __restrict__ out) {
    __shared__ double sh[128];
    int t = threadIdx.x;
    double c = 0.0;
    if (t < BB) {
        const long long C = (long long)NN * (long long)(NN + 1) * (long long)(NN + 1);
        double sxx = (double)((long long)g_sxx[t] - C) * 0.25;
        double syy = (double)((long long)g_syy[t] - C) * 0.25;
        double sxy = (double)((long long)g_sxy[t] - C) * 0.25;
        c = sxy / sqrt(sxx * syy + 1e-8);
    }
    sh[t] = c;
    __syncthreads();
    for (int s = 64; s; s >>= 1) { if (t < s) sh[t] += sh[t + s]; __syncthreads(); }
    double mean = sh[0] / (double)BB;
    __syncthreads();
    double d = 0.0;
    if (t < BB) { double e = c - mean; d = e * e; }
    sh[t] = d;
    __syncthreads();
    for (int s = 64; s; s >>= 1) { if (t < s) sh[t] += sh[t + s]; __syncthreads(); }
    if (t == 0) {
        double sd = sqrt(sh[0] / (double)BB) + 1e-8;
        out[0] = (float)(-(mean / sd) + 0.1 * sd);
    }
}

extern "C" void kernel_launch(void* const* d_in, const int* in_sizes, int n_in,
                              void* d_out, int out_size) {
    const float* pred  = (const float*)d_in[0];
    const float* trueY = (const float*)d_in[1];

    unsigned int *ch, *cs, *cur;
    unsigned char* tmp;
    cudaGetSymbolAddress((void**)&ch,  g_ch);
    cudaGetSymbolAddress((void**)&cs,  g_cs);
    cudaGetSymbolAddress((void**)&cur, g_cur);
    cudaGetSymbolAddress((void**)&tmp, g_temp);

    cudaStream_t s0 = (cudaStream_t)0;
    const int QBLKS = (TOT / 4) / 256;     // 23040 exact
    const int RBLKS = BB * NBC;            // 92160

    cudaMemsetAsync(ch, 0, (size_t)NCH * sizeof(unsigned int), s0);
    zero_sums_kernel<<<1, 128, 0, s0>>>();

    hist_kernel<<<QBLKS, 256, 0, s0>>>((const float4*)pred, (const float4*)trueY);

    {   // scan of tiny coarse hist
        size_t tb = 0;
        cub::DeviceScan::ExclusiveSum(nullptr, tb, ch, cs, NCH, s0);
        if (tb > (size_t)(4u << 20)) return;
        cub::DeviceScan::ExclusiveSum(tmp, tb, ch, cs, NCH, s0);
    }
    cudaMemcpyAsync(cur, cs, (size_t)NCH * sizeof(unsigned int),
                    cudaMemcpyDeviceToDevice, s0);

    scatter_kernel<<<QBLKS, 256, 0, s0>>>((const float4*)pred, (const float4*)trueY);

    rank_kernel<0><<<RBLKS, 256, 0, s0>>>();   // pred: u2 + sxx
    rank_kernel<1><<<RBLKS, 256, 0, s0>>>();   // true: syy + sxy
    final_kernel<<<1, 128, 0, s0>>>((float*)d_out);
}

// round 9
// speedup vs baseline: 2.3820x; 2.3820x over previous
#include <cuda_runtime.h>
#include <cuda_bf16.h>
#include <cub/cub.cuh>

#define BB    90
#define LOGN  18
#define NN    (1 << LOGN)              // 262144
#define TOT   (BB * NN)
#define G     10                       // rows per chunk (90 = 9*10)
#define NCHK  (BB / G)                 // 9 chunks
#define SLABE (2 * G * NN)             // 5,242,880 slab elements / buckets

// -------- static device scratch (all chunk slabs are L2-resident) --------
static __device__ __align__(256) unsigned int g_hist[SLABE];    // 21 MB
static __device__ __align__(256) unsigned int g_stash[SLABE];   // 21 MB fkeys, orig order
static __device__ __align__(256) unsigned int g_keys[SLABE];    // 21 MB fkeys, bucket order
static __device__ __align__(256) unsigned char g_temp[4u << 20];
static __device__ unsigned long long g_sxx[BB], g_syy[BB], g_sxy[BB];

__device__ __forceinline__ unsigned int fkey(float f) {
    f = f + 0.0f;                       // canonicalize -0 -> +0
    unsigned int u = __float_as_uint(f);
    return (u & 0x80000000u) ? ~u : (u | 0x80000000u);
}
__device__ __forceinline__ float inv_fkey(unsigned int fk) {
    unsigned int u = (fk & 0x80000000u) ? (fk & 0x7FFFFFFFu) : ~fk;
    return __uint_as_float(u);
}
// exactly weakly-monotone 18-bit bucketization (ties never split buckets)
__device__ __forceinline__ unsigned int digit_of(float x) {
    float t = fmaf(x, 32768.0f, 131072.0f);
    t = fminf(fmaxf(t, 0.0f), 262143.0f);
    return (unsigned int)t;
}

__global__ void zero_sums_kernel() {
    int t = threadIdx.x;
    if (t < BB) { g_sxx[t] = 0ull; g_syy[t] = 0ull; g_sxy[t] = 0ull; }
}

// -------- chunk pass 1: read inputs once, stash fkeys, fine histogram --------
__global__ void hist_kernel(const float4* __restrict__ p, const float4* __restrict__ t,
                            int rowbase) {
    int e0 = (blockIdx.x * 256 + threadIdx.x) * 4;       // slab element index
    int seg = e0 >> LOGN;                                 // 0..2G-1
    int within = e0 & (NN - 1);
    bool isT = seg >= G;
    int r = isT ? seg - G : seg;
    const float4* src = isT ? t : p;
    float4 v = src[(((unsigned)(rowbase + r) << LOGN) + (unsigned)within) >> 2];
    unsigned int base = (unsigned int)seg << LOGN;
    float av[4] = {v.x, v.y, v.z, v.w};
    uint4 st;
    unsigned int* sp = (unsigned int*)&st;
#pragma unroll
    for (int j = 0; j < 4; ++j) {
        sp[j] = fkey(av[j]);
        atomicAdd(&g_hist[base + digit_of(av[j])], 1u);
    }
    ((uint4*)g_stash)[e0 >> 2] = st;
}

// -------- chunk pass 2: scatter fkeys into bucket-ordered slab --------
__global__ void scatter_kernel() {
    int e0 = (blockIdx.x * 256 + threadIdx.x) * 4;
    unsigned int base = ((unsigned int)e0 >> LOGN) << LOGN;
    uint4 sv = ((const uint4*)g_stash)[e0 >> 2];
    unsigned int f[4] = {sv.x, sv.y, sv.z, sv.w};
#pragma unroll
    for (int j = 0; j < 4; ++j) {
        unsigned int d = digit_of(inv_fkey(f[j]));
        unsigned int pos = atomicAdd(&g_hist[base + d], 1u);
        g_keys[pos] = f[j];
    }
}

__device__ __forceinline__ long long block_reduce_ll(long long v, long long* red) {
    for (int o = 16; o; o >>= 1) v += __shfl_down_sync(0xFFFFFFFFu, v, o);
    int w = threadIdx.x >> 5, lane = threadIdx.x & 31;
    if (lane == 0) red[w] = v;
    __syncthreads();
    if (w == 0) {
        v = (lane < 8) ? red[lane] : 0ll;
        for (int o = 4; o; o >>= 1) v += __shfl_down_sync(0xFFFFFFFFu, v, o);
    }
    return v;   // valid in thread 0
}

// 2*tie-avg-rank from bucket extents [s,e) (hist holds ENDS after scatter)
__device__ __forceinline__ int rank2_of(unsigned int sb, unsigned int lbase,
                                        unsigned int fk) {
    unsigned int s = sb ? g_hist[sb - 1] : 0u;
    unsigned int e = g_hist[sb];
    int c_less = 0, c_eq = 1;
    if (e - s > 1u) {
        c_eq = 0;
        for (unsigned int i = s; i < e; ++i) {
            unsigned int f = g_keys[i];
            c_less += (f < fk);
            c_eq   += (f == fk);
        }
    }
    return 2 * (int)(s - lbase + (unsigned int)c_less) + c_eq + 1;
}

// -------- chunk pass 3: fused pred+true ranks and moment sums --------
__global__ void rank_kernel(int rowbase) {
    __shared__ long long red[8];
    int rl = blockIdx.x >> 8;                              // row within chunk (256 blk/row)
    int idx0 = ((blockIdx.x & 255) * 256 + threadIdx.x) * 4;
    unsigned int segP = (unsigned int)rl;
    unsigned int segT = (unsigned int)(G + rl);
    uint4 pv = ((const uint4*)g_stash)[((segP << LOGN) + (unsigned)idx0) >> 2];
    uint4 tv = ((const uint4*)g_stash)[((segT << LOGN) + (unsigned)idx0) >> 2];
    unsigned int pf[4] = {pv.x, pv.y, pv.z, pv.w};
    unsigned int tf[4] = {tv.x, tv.y, tv.z, tv.w};
    unsigned int lbP = segP << LOGN, lbT = segT << LOGN;
    long long sxx = 0, syy = 0, sxy = 0;
#pragma unroll
    for (int j = 0; j < 4; ++j) {
        unsigned int dP = digit_of(inv_fkey(pf[j]));
        unsigned int dT = digit_of(inv_fkey(tf[j]));
        int r2p = rank2_of(lbP + dP, lbP, pf[j]);
        int r2t = rank2_of(lbT + dT, lbT, tf[j]);
        sxx += (long long)r2p * r2p;
        syy += (long long)r2t * r2t;
        sxy += (long long)r2p * r2t;
    }
    sxx = block_reduce_ll(sxx, red); __syncthreads();
    syy = block_reduce_ll(syy, red); __syncthreads();
    sxy = block_reduce_ll(sxy, red);
    if (threadIdx.x == 0) {
        int row = rowbase + rl;
        atomicAdd(&g_sxx[row], (unsigned long long)sxx);
        atomicAdd(&g_syy[row], (unsigned long long)syy);
        atomicAdd(&g_sxy[row], (unsigned long long)sxy);
    }
}

// -------- final: per-row corr -> ICIR loss --------
__global__ void final_kernel(float* __restrict__ out) {
    __shared__ double sh[128];
    int t = threadIdx.x;
    double c = 0.0;
    if (t < BB) {
        const long long C = (long long)NN * (long long)(NN + 1) * (long long)(NN + 1);
        double sxx = (double)((long long)g_sxx[t] - C) * 0.25;
        double syy = (double)((long long)g_syy[t] - C) * 0.25;
        double sxy = (double)((long long)g_sxy[t] - C) * 0.25;
        c = sxy / sqrt(sxx * syy + 1e-8);
    }
    sh[t] = c;
    __syncthreads();
    for (int s = 64; s; s >>= 1) { if (t < s) sh[t] += sh[t + s]; __syncthreads(); }
    double mean = sh[0] / (double)BB;
    __syncthreads();
    double d = 0.0;
    if (t < BB) { double e = c - mean; d = e * e; }
    sh[t] = d;
    __syncthreads();
    for (int s = 64; s; s >>= 1) { if (t < s) sh[t] += sh[t + s]; __syncthreads(); }
    if (t == 0) {
        double sd = sqrt(sh[0] / (double)BB) + 1e-8;
        out[0] = (float)(-(mean / sd) + 0.1 * sd);
    }
}

extern "C" void kernel_launch(void* const* d_in, const int* in_sizes, int n_in,
                              void* d_out, int out_size) {
    const float* pred  = (const float*)d_in[0];
    const float* trueY = (const float*)d_in[1];

    unsigned int* hist;
    unsigned char* tmp;
    cudaGetSymbolAddress((void**)&hist, g_hist);
    cudaGetSymbolAddress((void**)&tmp,  g_temp);

    cudaStream_t s0 = (cudaStream_t)0;
    const int SBLKS = SLABE / 1024;     // 5120: hist/scatter (4 elem/thread, 256 thr)
    const int RBLKS = G * 256;          // 2560: rank (4 elem/thread over G rows)

    zero_sums_kernel<<<1, 128, 0, s0>>>();

    for (int c = 0; c < NCHK; ++c) {
        int rowbase = c * G;
        cudaMemsetAsync(hist, 0, (size_t)SLABE * sizeof(unsigned int), s0);
        hist_kernel<<<SBLKS, 256, 0, s0>>>((const float4*)pred, (const float4*)trueY,
                                           rowbase);
        {
            size_t tb = 0;
            cub::DeviceScan::ExclusiveSum(nullptr, tb, hist, hist, SLABE, s0);
            if (tb > (size_t)(4u << 20)) return;
            cub::DeviceScan::ExclusiveSum(tmp, tb, hist, hist, SLABE, s0);
        }
        scatter_kernel<<<SBLKS, 256, 0, s0>>>();
        rank_kernel<<<RBLKS, 256, 0, s0>>>(rowbase);
    }

    final_kernel<<<1, 128, 0, s0>>>((float*)d_out);
}